// round 14
// baseline (speedup 1.0000x reference)
#include <cuda_runtime.h>
#include <cuda_bf16.h>
#include <cuda_fp16.h>
#include <cstdint>

#define N_NODES 50000
#define F1 128
#define NCLS 16
#define EMAX 1600000
#define NB_SCAN ((N_NODES + 255) / 256)   // 196

// ---------------- scratch (static device globals; no allocation) ----------------
__device__ int    g_cnt[N_NODES];
__device__ int    g_start[N_NODES + 1];
__device__ int    g_cursor[N_NODES];
__device__ int    g_srcl[EMAX];
__device__ float  g_inv[N_NODES];
__device__ __half g_Ah[N_NODES * F1];     // gemm output h (UNSCALED), fp16
__device__ float  g_C[N_NODES * F1];      // relu(layer1 aggregate), fp32
__device__ int    g_bsum[256];
__device__ int    g_boff[256];
__device__ int    g_is64;
// pre-split weights, padded to K=512, layout [n][512] bf16
__device__ __nv_bfloat16 g_W1hi[128 * 512];
__device__ __nv_bfloat16 g_W1lo[128 * 512];
__device__ __nv_bfloat16 g_W2hi[128 * 512];
__device__ __nv_bfloat16 g_W2lo[128 * 512];

// ---------------- mma/ldmatrix/cp.async wrappers (base ISA, sm_80+) ----------------
__device__ __forceinline__ uint32_t s2u(const void* p) {
    uint32_t a;
    asm("{ .reg .u64 t; cvta.to.shared.u64 t, %1; cvt.u32.u64 %0, t; }" : "=r"(a) : "l"(p));
    return a;
}
__device__ __forceinline__ void ldsm4(uint32_t& r0, uint32_t& r1, uint32_t& r2, uint32_t& r3,
                                      uint32_t addr) {
    asm volatile("ldmatrix.sync.aligned.m8n8.x4.shared.b16 {%0,%1,%2,%3}, [%4];"
                 : "=r"(r0), "=r"(r1), "=r"(r2), "=r"(r3) : "r"(addr));
}
__device__ __forceinline__ void mma16816(float* c, const uint32_t* a, const uint32_t* b) {
    asm volatile(
        "mma.sync.aligned.m16n8k16.row.col.f32.bf16.bf16.f32 "
        "{%0,%1,%2,%3}, {%4,%5,%6,%7}, {%8,%9}, {%0,%1,%2,%3};"
        : "+f"(c[0]), "+f"(c[1]), "+f"(c[2]), "+f"(c[3])
        : "r"(a[0]), "r"(a[1]), "r"(a[2]), "r"(a[3]), "r"(b[0]), "r"(b[1]));
}
__device__ __forceinline__ void cp16(uint32_t smem_dst, const void* gmem_src) {
    asm volatile("cp.async.cg.shared.global [%0], [%1], 16;"
                 :: "r"(smem_dst), "l"(gmem_src) : "memory");
}
__device__ __forceinline__ void cp_commit() {
    asm volatile("cp.async.commit_group;" ::: "memory");
}
__device__ __forceinline__ void cp_wait0() {
    asm volatile("cp.async.wait_group 0;" ::: "memory");
}

// ---------------- fused init: zero counts + dtype detect ----------------
__global__ void k_init(const int* ei) {
    int i = blockIdx.x * blockDim.x + threadIdx.x;
    if (i < N_NODES) g_cnt[i] = 0;
    if (i == 0) {
        int ok64 = 1;
        #pragma unroll 1
        for (int q = 0; q < 64; q++) ok64 &= (ei[2 * q + 1] == 0);
        g_is64 = ok64;
    }
}

// ---------------- CSR build ----------------
__global__ __launch_bounds__(256) void k_hist(const void* idx, long long E) {
    long long e = (long long)blockIdx.x * blockDim.x + threadIdx.x;
    if (e >= E) return;
    int d;
    if (g_is64) d = (int)((const long long*)idx)[E + e];
    else        d = ((const int*)idx)[E + e];
    atomicAdd(&g_cnt[d], 1);
}

__global__ __launch_bounds__(256) void k_scan1() {
    int i = blockIdx.x * 256 + threadIdx.x;
    int lane = threadIdx.x & 31, wid = threadIdx.x >> 5;
    int c = (i < N_NODES) ? g_cnt[i] : 0;
    int s = c;
    #pragma unroll
    for (int off = 16; off; off >>= 1) s += __shfl_xor_sync(0xffffffffu, s, off);
    __shared__ int ws[8];
    if (lane == 0) ws[wid] = s;
    __syncthreads();
    if (threadIdx.x == 0) {
        int tot = 0;
        #pragma unroll
        for (int w = 0; w < 8; w++) tot += ws[w];
        g_bsum[blockIdx.x] = tot;
    }
}

__global__ __launch_bounds__(256) void k_scan2() {
    __shared__ int s[256];
    int t = threadIdx.x;
    int v = (t < NB_SCAN) ? g_bsum[t] : 0;
    s[t] = v;
    __syncthreads();
    for (int off = 1; off < 256; off <<= 1) {
        int u = (t >= off) ? s[t - off] : 0;
        __syncthreads();
        s[t] += u;
        __syncthreads();
    }
    g_boff[t] = s[t] - v;
    if (t == 255) g_start[N_NODES] = s[255];
}

__global__ __launch_bounds__(256) void k_scan3() {
    int i = blockIdx.x * 256 + threadIdx.x;
    int t = threadIdx.x, lane = t & 31, wid = t >> 5;
    int c = (i < N_NODES) ? g_cnt[i] : 0;
    int incl = c;
    #pragma unroll
    for (int off = 1; off < 32; off <<= 1) {
        int u = __shfl_up_sync(0xffffffffu, incl, off);
        if (lane >= off) incl += u;
    }
    __shared__ int ws[8];
    if (lane == 31) ws[wid] = incl;
    __syncthreads();
    if (t == 0) {
        int run = 0;
        #pragma unroll
        for (int w = 0; w < 8; w++) { int x = ws[w]; ws[w] = run; run += x; }
    }
    __syncthreads();
    if (i < N_NODES) {
        int excl = incl - c + ws[wid] + g_boff[blockIdx.x];
        g_start[i]  = excl;
        g_cursor[i] = excl;
        g_inv[i]    = rsqrtf((float)c + 1.0f);
    }
}

__global__ __launch_bounds__(256) void k_fill(const void* idx, long long E) {
    long long e = (long long)blockIdx.x * blockDim.x + threadIdx.x;
    if (e >= E) return;
    int s, d;
    if (g_is64) {
        s = (int)((const long long*)idx)[e];
        d = (int)((const long long*)idx)[E + e];
    } else {
        s = ((const int*)idx)[e];
        d = ((const int*)idx)[E + e];
    }
    int pos = atomicAdd(&g_cursor[d], 1);
    g_srcl[pos] = s;
}

// ---------------- weight pre-split: W[n][k] fp32 -> hi/lo bf16 padded [n][512] ----------------
__global__ __launch_bounds__(256) void k_wsplit(const float* __restrict__ W,
                                                __nv_bfloat16* __restrict__ hi,
                                                __nv_bfloat16* __restrict__ lo, int K) {
    int i = blockIdx.x * 256 + threadIdx.x;
    if (i >= 128 * 512) return;
    int n = i >> 9, k = i & 511;
    float v = (k < K) ? W[n * K + k] : 0.0f;
    __nv_bfloat16 h = __float2bfloat16(v);
    hi[i] = h;
    lo[i] = __float2bfloat16(v - __bfloat162float(h));
}

// ---------------- split-bf16 HMMA GEMM, 4 warps, warp tile 64x64, cp.async W ----------------
// Ah[row, 0:128] = X[row,:] @ W^T (UNSCALED), fp32 accum via hi/lo split, fp16 output.
// CTA 128x128, 128 threads (2m x 2n warps, warp tile 64x64) -> MMA:LDSM ratio 6 (was 4).
// X: reg-prefetch + in-thread split (thread t owns row t, 32 floats/chunk).
// W: cp.async direct to smem; W(ch+1) issued after sync(ch) (all MMA(ch-1) retired),
//    cp_wait0 before sync(ch) publishes W(ch). Single __syncthreads per chunk.
#define LDB 80
#define TILE_B (128 * LDB)          // 10240
#define CH_BUF (4 * TILE_B)         // 40960: [XHI, XLO, WHI, WLO]
#define GEMM_SMEM (2 * CH_BUF)      // 81920

template <int K>
__global__ __launch_bounds__(128, 2) void k_gemm_mma(const float* __restrict__ X,
                                                     const __nv_bfloat16* __restrict__ Whi,
                                                     const __nv_bfloat16* __restrict__ Wlo,
                                                     __half* __restrict__ Ah) {
    extern __shared__ __align__(16) char smem[];
    const uint32_t sb = s2u(smem);
    const int t = threadIdx.x;
    const int lane = t & 31, wid = t >> 5;
    const int wm = wid >> 1, wn = wid & 1;
    const int m0 = blockIdx.x * 128;
    const int NT = (K + 31) / 32;

    const int xr = m0 + t;                 // thread t owns X row t of the tile
    const bool rok = xr < N_NODES;
    const float* Xrow = X + (size_t)xr * K;
    const uint32_t xbase = (uint32_t)t * LDB;

    const int a_row  = lane & 15;
    const int a_koff = ((lane >> 4) & 1) * 16;
    const int b_row  = ((lane >> 4) & 1) * 8 + (lane & 7);
    const int b_koff = ((lane >> 3) & 1) * 16;

    float c[4][8][4];
    #pragma unroll
    for (int i = 0; i < 4; i++)
        #pragma unroll
        for (int j = 0; j < 8; j++)
            #pragma unroll
            for (int q = 0; q < 4; q++) c[i][j][q] = 0.0f;

    float v[32];

#define LOADX(CH) do {                                                          \
        const int kc_ = (CH) * 32;                                              \
        _Pragma("unroll")                                                       \
        for (int q = 0; q < 8; q++) {                                           \
            if (rok && kc_ + q * 4 + 4 <= K) {                                  \
                float4 f = *(const float4*)(Xrow + kc_ + q * 4);                \
                v[q * 4 + 0] = f.x; v[q * 4 + 1] = f.y;                         \
                v[q * 4 + 2] = f.z; v[q * 4 + 3] = f.w;                         \
            } else {                                                            \
                v[q * 4 + 0] = 0.f; v[q * 4 + 1] = 0.f;                         \
                v[q * 4 + 2] = 0.f; v[q * 4 + 3] = 0.f;                         \
            }                                                                   \
        }                                                                       \
    } while (0)

    // cp.async W chunk CH into buffer BUFI (thread t copies W row t: 4x16B hi + 4x16B lo)
#define CPW(CH, BUFI) do {                                                      \
        const uint32_t wb_ = sb + (uint32_t)(BUFI) * CH_BUF + xbase;            \
        const __nv_bfloat16* wh_ = Whi + (size_t)t * 512 + (CH) * 32;           \
        const __nv_bfloat16* wl_ = Wlo + (size_t)t * 512 + (CH) * 32;           \
        _Pragma("unroll")                                                       \
        for (int i = 0; i < 4; i++) {                                           \
            cp16(wb_ + 2 * TILE_B + i * 16, wh_ + i * 8);                       \
            cp16(wb_ + 3 * TILE_B + i * 16, wl_ + i * 8);                       \
        }                                                                       \
        cp_commit();                                                            \
    } while (0)

    LOADX(0);
    CPW(0, 0);

    for (int ch = 0; ch < NT; ch++) {
        const uint32_t bo = (uint32_t)(ch & 1) * CH_BUF;

        // ---- convert chunk ch (regs) -> split bf16 X tiles in buf[ch&1] ----
        {
            uint32_t hh[16], ll[16];
            #pragma unroll
            for (int p = 0; p < 16; p++) {
                __nv_bfloat16 ha = __float2bfloat16(v[2 * p]);
                __nv_bfloat16 hb = __float2bfloat16(v[2 * p + 1]);
                __nv_bfloat16 la = __float2bfloat16(v[2 * p]     - __bfloat162float(ha));
                __nv_bfloat16 lb = __float2bfloat16(v[2 * p + 1] - __bfloat162float(hb));
                hh[p] = (uint32_t)__bfloat16_as_ushort(ha) | ((uint32_t)__bfloat16_as_ushort(hb) << 16);
                ll[p] = (uint32_t)__bfloat16_as_ushort(la) | ((uint32_t)__bfloat16_as_ushort(lb) << 16);
            }
            char* xb = smem + bo + xbase;
            #pragma unroll
            for (int i = 0; i < 4; i++) {
                *(uint4*)(xb + i * 16)          = make_uint4(hh[4*i], hh[4*i+1], hh[4*i+2], hh[4*i+3]);
                *(uint4*)(xb + TILE_B + i * 16) = make_uint4(ll[4*i], ll[4*i+1], ll[4*i+2], ll[4*i+3]);
            }
        }

        // ---- issue next chunk's X loads (consumed next iteration) ----
        if (ch + 1 < NT) LOADX(ch + 1);

        cp_wait0();            // W(ch) resident
        __syncthreads();       // publish X(ch)+W(ch); implies MMA(ch-1) retired

        if (ch + 1 < NT) CPW(ch + 1, (ch + 1) & 1);   // overlaps MMA(ch); safe per sync

        // ---- MMA on buf[ch&1] ----
        #pragma unroll
        for (int kb = 0; kb < 2; kb++) {
            uint32_t ah[4][4], al[4][4], bh[8][2], bl[8][2];
            #pragma unroll
            for (int mt = 0; mt < 4; mt++) {
                uint32_t ro = (uint32_t)(wm * 64 + mt * 16 + a_row) * LDB + kb * 32 + a_koff;
                ldsm4(ah[mt][0], ah[mt][1], ah[mt][2], ah[mt][3], sb + bo + ro);
                ldsm4(al[mt][0], al[mt][1], al[mt][2], al[mt][3], sb + bo + TILE_B + ro);
            }
            #pragma unroll
            for (int p = 0; p < 4; p++) {
                uint32_t ro = (uint32_t)(wn * 64 + p * 16 + b_row) * LDB + kb * 32 + b_koff;
                uint32_t r0, r1, r2, r3;
                ldsm4(r0, r1, r2, r3, sb + bo + 2 * TILE_B + ro);
                bh[2 * p][0] = r0; bh[2 * p][1] = r1;
                bh[2 * p + 1][0] = r2; bh[2 * p + 1][1] = r3;
                ldsm4(r0, r1, r2, r3, sb + bo + 3 * TILE_B + ro);
                bl[2 * p][0] = r0; bl[2 * p][1] = r1;
                bl[2 * p + 1][0] = r2; bl[2 * p + 1][1] = r3;
            }
            #pragma unroll
            for (int mt = 0; mt < 4; mt++)
                #pragma unroll
                for (int nt = 0; nt < 8; nt++) {
                    mma16816(c[mt][nt], ah[mt], bh[nt]);
                    mma16816(c[mt][nt], ah[mt], bl[nt]);
                    mma16816(c[mt][nt], al[mt], bh[nt]);
                }
        }
    }
#undef LOADX
#undef CPW

    // ---- epilogue: store fp16 (no scaling; inv applied in aggregation) ----
    #pragma unroll
    for (int mt = 0; mt < 4; mt++)
        #pragma unroll
        for (int g2 = 0; g2 < 2; g2++) {
            int row = m0 + wm * 64 + mt * 16 + (lane >> 2) + g2 * 8;
            if (row < N_NODES) {
                __half* pr = Ah + (size_t)row * F1 + wn * 64 + (lane & 3) * 2;
                #pragma unroll
                for (int nt = 0; nt < 8; nt++) {
                    __half2 o = __floats2half2_rn(c[mt][nt][g2 * 2 + 0],
                                                  c[mt][nt][g2 * 2 + 1]);
                    *(__half2*)(pr + nt * 8) = o;
                }
            }
        }
}

// ---------------- half2 gather helper ----------------
__device__ __forceinline__ float4 ld_row4(const uint2* A2, int row, int lane) {
    uint2 u = A2[(size_t)row * 32 + lane];
    float2 f0 = __half22float2(*(__half2*)&u.x);
    float2 f1 = __half22float2(*(__half2*)&u.y);
    return make_float4(f0.x, f0.y, f1.x, f1.y);
}

// ---------------- layer-1 aggregation: acc = sum inv[src]*h[src] (+self), relu(inv*acc) ----------------
__global__ __launch_bounds__(256) void k_agg1() {
    long long t = (long long)blockIdx.x * blockDim.x + threadIdx.x;
    int w    = (int)(t >> 5);
    int lane = (int)(t & 31);
    if (w >= N_NODES) return;
    const uint2* A2 = (const uint2*)g_Ah;
    float s = g_inv[w];

    float4 v = ld_row4(A2, w, lane);
    float4 acc = make_float4(v.x * s, v.y * s, v.z * s, v.w * s);   // self loop

    int p  = g_start[w];
    int s1 = g_start[w + 1];
    for (; p + 4 <= s1; p += 4) {
        int i0 = g_srcl[p], i1 = g_srcl[p + 1], i2 = g_srcl[p + 2], i3 = g_srcl[p + 3];
        float w0 = g_inv[i0], w1 = g_inv[i1], w2 = g_inv[i2], w3 = g_inv[i3];
        float4 v0 = ld_row4(A2, i0, lane);
        float4 v1 = ld_row4(A2, i1, lane);
        float4 v2 = ld_row4(A2, i2, lane);
        float4 v3 = ld_row4(A2, i3, lane);
        acc.x += (v0.x * w0 + v1.x * w1) + (v2.x * w2 + v3.x * w3);
        acc.y += (v0.y * w0 + v1.y * w1) + (v2.y * w2 + v3.y * w3);
        acc.z += (v0.z * w0 + v1.z * w1) + (v2.z * w2 + v3.z * w3);
        acc.w += (v0.w * w0 + v1.w * w1) + (v2.w * w2 + v3.w * w3);
    }
    for (; p < s1; p++) {
        int i = g_srcl[p];
        float wi = g_inv[i];
        float4 u = ld_row4(A2, i, lane);
        acc.x += u.x * wi; acc.y += u.y * wi; acc.z += u.z * wi; acc.w += u.w * wi;
    }
    acc.x = fmaxf(acc.x * s, 0.f);
    acc.y = fmaxf(acc.y * s, 0.f);
    acc.z = fmaxf(acc.z * s, 0.f);
    acc.w = fmaxf(acc.w * s, 0.f);
    ((float4*)g_C)[(size_t)w * 32 + lane] = acc;
}

// ---------------- layer-2 aggregation + fused linear head ----------------
__global__ __launch_bounds__(256) void k_agg2(const float* __restrict__ Wlin,
                                              float* __restrict__ out) {
    __shared__ __align__(16) float Wl[NCLS * F1];
    int t = threadIdx.x;
    #pragma unroll
    for (int i = 0; i < 8; i++) Wl[t + i * 256] = Wlin[t + i * 256];
    __syncthreads();

    int w    = blockIdx.x * 8 + (t >> 5);
    int lane = t & 31;
    if (w >= N_NODES) return;
    const uint2* A2 = (const uint2*)g_Ah;
    float s = g_inv[w];

    float4 v = ld_row4(A2, w, lane);
    float4 acc = make_float4(v.x * s, v.y * s, v.z * s, v.w * s);

    int p  = g_start[w];
    int s1 = g_start[w + 1];
    for (; p + 4 <= s1; p += 4) {
        int i0 = g_srcl[p], i1 = g_srcl[p + 1], i2 = g_srcl[p + 2], i3 = g_srcl[p + 3];
        float w0 = g_inv[i0], w1 = g_inv[i1], w2 = g_inv[i2], w3 = g_inv[i3];
        float4 v0 = ld_row4(A2, i0, lane);
        float4 v1 = ld_row4(A2, i1, lane);
        float4 v2 = ld_row4(A2, i2, lane);
        float4 v3 = ld_row4(A2, i3, lane);
        acc.x += (v0.x * w0 + v1.x * w1) + (v2.x * w2 + v3.x * w3);
        acc.y += (v0.y * w0 + v1.y * w1) + (v2.y * w2 + v3.y * w3);
        acc.z += (v0.z * w0 + v1.z * w1) + (v2.z * w2 + v3.z * w3);
        acc.w += (v0.w * w0 + v1.w * w1) + (v2.w * w2 + v3.w * w3);
    }
    for (; p < s1; p++) {
        int i = g_srcl[p];
        float wi = g_inv[i];
        float4 u = ld_row4(A2, i, lane);
        acc.x += u.x * wi; acc.y += u.y * wi; acc.z += u.z * wi; acc.w += u.w * wi;
    }
    acc.x *= s; acc.y *= s; acc.z *= s; acc.w *= s;

    #pragma unroll
    for (int cc = 0; cc < NCLS; cc++) {
        float4 wv = *(const float4*)&Wl[cc * F1 + lane * 4];
        float pd = acc.x * wv.x + acc.y * wv.y + acc.z * wv.z + acc.w * wv.w;
        pd += __shfl_xor_sync(0xffffffffu, pd, 16);
        pd += __shfl_xor_sync(0xffffffffu, pd, 8);
        pd += __shfl_xor_sync(0xffffffffu, pd, 4);
        pd += __shfl_xor_sync(0xffffffffu, pd, 2);
        pd += __shfl_xor_sync(0xffffffffu, pd, 1);
        if (lane == 0) out[(size_t)w * NCLS + cc] = pd;
    }
}

// ---------------- launch ----------------
extern "C" void kernel_launch(void* const* d_in, const int* in_sizes, int n_in,
                              void* d_out, int out_size) {
    const float* x    = (const float*)d_in[0];
    const void*  ei   = d_in[1];
    const float* W1   = (const float*)d_in[2];
    const float* W2   = (const float*)d_in[3];
    const float* Wlin = (const float*)d_in[4];
    float* out = (float*)d_out;

    long long E = (long long)in_sizes[1] / 2;

    __half* Ah;
    float* C;
    __nv_bfloat16 *w1h, *w1l, *w2h, *w2l;
    cudaGetSymbolAddress((void**)&Ah, g_Ah);
    cudaGetSymbolAddress((void**)&C, g_C);
    cudaGetSymbolAddress((void**)&w1h, g_W1hi);
    cudaGetSymbolAddress((void**)&w1l, g_W1lo);
    cudaGetSymbolAddress((void**)&w2h, g_W2hi);
    cudaGetSymbolAddress((void**)&w2l, g_W2lo);

    // >48KB dynamic smem opt-in (idempotent, capture-safe host call)
    cudaFuncSetAttribute(k_gemm_mma<500>, cudaFuncAttributeMaxDynamicSharedMemorySize, GEMM_SMEM);
    cudaFuncSetAttribute(k_gemm_mma<128>, cudaFuncAttributeMaxDynamicSharedMemorySize, GEMM_SMEM);

    const int T = 256;
    int nodeBlocks = (N_NODES + T - 1) / T;
    int gemmBlocks = (N_NODES + 127) / 128;   // 391
    int edgeBlocks = (int)((E + T - 1) / T);
    int aggBlocks  = (int)(((long long)N_NODES * 32 + T - 1) / T);
    int wsBlocks   = (128 * 512 + T - 1) / T;

    // order chosen so launch index 3 (the ncu capture slot) = k_gemm_mma<500>
    k_init<<<nodeBlocks, T>>>((const int*)ei);                          // 0
    k_wsplit<<<wsBlocks, T>>>(W1, w1h, w1l, 500);                       // 1
    k_hist<<<edgeBlocks, T>>>(ei, E);                                   // 2
    k_gemm_mma<500><<<gemmBlocks, 128, GEMM_SMEM>>>(x, w1h, w1l, Ah);   // 3  <- profiled
    k_scan1<<<NB_SCAN, T>>>();                                          // 4
    k_scan2<<<1, T>>>();                                                // 5
    k_scan3<<<NB_SCAN, T>>>();                                          // 6
    k_fill<<<edgeBlocks, T>>>(ei, E);                                   // 7
    k_agg1<<<aggBlocks, T>>>();                                         // 8
    k_wsplit<<<wsBlocks, T>>>(W2, w2h, w2l, 128);                       // 9
    k_gemm_mma<128><<<gemmBlocks, 128, GEMM_SMEM>>>(C, w2h, w2l, Ah);   // 10
    k_agg2<<<(N_NODES + 7) / 8, T>>>(Wlin, out);                        // 11
}

// round 15
// speedup vs baseline: 1.1520x; 1.1520x over previous
#include <cuda_runtime.h>
#include <cuda_bf16.h>
#include <cuda_fp16.h>
#include <cstdint>

#define N_NODES 50000
#define F1 128
#define NCLS 16
#define EMAX 1600000
#define NB_SCAN ((N_NODES + 255) / 256)   // 196

// ---------------- scratch (static device globals; no allocation) ----------------
__device__ int    g_cnt[N_NODES];
__device__ int    g_start[N_NODES + 1];
__device__ int    g_cursor[N_NODES];
__device__ int    g_srcl[EMAX];
__device__ float  g_inv[N_NODES];
__device__ __half g_Ah[N_NODES * F1];     // gemm output h (UNSCALED), fp16
__device__ float  g_C[N_NODES * F1];      // relu(layer1 aggregate), fp32
__device__ int    g_bsum[256];
__device__ int    g_boff[256];
__device__ int    g_is64;
// pre-split weights, padded to K=512, layout [n][512] bf16
__device__ __nv_bfloat16 g_W1hi[128 * 512];
__device__ __nv_bfloat16 g_W1lo[128 * 512];
__device__ __nv_bfloat16 g_W2hi[128 * 512];
__device__ __nv_bfloat16 g_W2lo[128 * 512];

// ---------------- mma/ldmatrix wrappers (base ISA, sm_80+) ----------------
__device__ __forceinline__ uint32_t s2u(const void* p) {
    uint32_t a;
    asm("{ .reg .u64 t; cvta.to.shared.u64 t, %1; cvt.u32.u64 %0, t; }" : "=r"(a) : "l"(p));
    return a;
}
__device__ __forceinline__ void ldsm4(uint32_t& r0, uint32_t& r1, uint32_t& r2, uint32_t& r3,
                                      uint32_t addr) {
    asm volatile("ldmatrix.sync.aligned.m8n8.x4.shared.b16 {%0,%1,%2,%3}, [%4];"
                 : "=r"(r0), "=r"(r1), "=r"(r2), "=r"(r3) : "r"(addr));
}
__device__ __forceinline__ void mma16816(float* c, const uint32_t* a, const uint32_t* b) {
    asm volatile(
        "mma.sync.aligned.m16n8k16.row.col.f32.bf16.bf16.f32 "
        "{%0,%1,%2,%3}, {%4,%5,%6,%7}, {%8,%9}, {%0,%1,%2,%3};"
        : "+f"(c[0]), "+f"(c[1]), "+f"(c[2]), "+f"(c[3])
        : "r"(a[0]), "r"(a[1]), "r"(a[2]), "r"(a[3]), "r"(b[0]), "r"(b[1]));
}

// ---------------- fused init: zero counts + dtype detect ----------------
__global__ void k_init(const int* ei) {
    int i = blockIdx.x * blockDim.x + threadIdx.x;
    if (i < N_NODES) g_cnt[i] = 0;
    if (i == 0) {
        int ok64 = 1;
        #pragma unroll 1
        for (int q = 0; q < 64; q++) ok64 &= (ei[2 * q + 1] == 0);
        g_is64 = ok64;
    }
}

// ---------------- CSR build ----------------
__global__ __launch_bounds__(256) void k_hist(const void* idx, long long E) {
    long long e = (long long)blockIdx.x * blockDim.x + threadIdx.x;
    if (e >= E) return;
    int d;
    if (g_is64) d = (int)((const long long*)idx)[E + e];
    else        d = ((const int*)idx)[E + e];
    atomicAdd(&g_cnt[d], 1);
}

__global__ __launch_bounds__(256) void k_scan1() {
    int i = blockIdx.x * 256 + threadIdx.x;
    int lane = threadIdx.x & 31, wid = threadIdx.x >> 5;
    int c = (i < N_NODES) ? g_cnt[i] : 0;
    int s = c;
    #pragma unroll
    for (int off = 16; off; off >>= 1) s += __shfl_xor_sync(0xffffffffu, s, off);
    __shared__ int ws[8];
    if (lane == 0) ws[wid] = s;
    __syncthreads();
    if (threadIdx.x == 0) {
        int tot = 0;
        #pragma unroll
        for (int w = 0; w < 8; w++) tot += ws[w];
        g_bsum[blockIdx.x] = tot;
    }
}

__global__ __launch_bounds__(256) void k_scan2() {
    __shared__ int s[256];
    int t = threadIdx.x;
    int v = (t < NB_SCAN) ? g_bsum[t] : 0;
    s[t] = v;
    __syncthreads();
    for (int off = 1; off < 256; off <<= 1) {
        int u = (t >= off) ? s[t - off] : 0;
        __syncthreads();
        s[t] += u;
        __syncthreads();
    }
    g_boff[t] = s[t] - v;
    if (t == 255) g_start[N_NODES] = s[255];
}

__global__ __launch_bounds__(256) void k_scan3() {
    int i = blockIdx.x * 256 + threadIdx.x;
    int t = threadIdx.x, lane = t & 31, wid = t >> 5;
    int c = (i < N_NODES) ? g_cnt[i] : 0;
    int incl = c;
    #pragma unroll
    for (int off = 1; off < 32; off <<= 1) {
        int u = __shfl_up_sync(0xffffffffu, incl, off);
        if (lane >= off) incl += u;
    }
    __shared__ int ws[8];
    if (lane == 31) ws[wid] = incl;
    __syncthreads();
    if (t == 0) {
        int run = 0;
        #pragma unroll
        for (int w = 0; w < 8; w++) { int x = ws[w]; ws[w] = run; run += x; }
    }
    __syncthreads();
    if (i < N_NODES) {
        int excl = incl - c + ws[wid] + g_boff[blockIdx.x];
        g_start[i]  = excl;
        g_cursor[i] = excl;
        g_inv[i]    = rsqrtf((float)c + 1.0f);
    }
}

__global__ __launch_bounds__(256) void k_fill(const void* idx, long long E) {
    long long e = (long long)blockIdx.x * blockDim.x + threadIdx.x;
    if (e >= E) return;
    int s, d;
    if (g_is64) {
        s = (int)((const long long*)idx)[e];
        d = (int)((const long long*)idx)[E + e];
    } else {
        s = ((const int*)idx)[e];
        d = ((const int*)idx)[E + e];
    }
    int pos = atomicAdd(&g_cursor[d], 1);
    g_srcl[pos] = s;
}

// ---------------- weight pre-split: W[n][k] fp32 -> hi/lo bf16 padded [n][512] ----------------
__global__ __launch_bounds__(256) void k_wsplit(const float* __restrict__ W,
                                                __nv_bfloat16* __restrict__ hi,
                                                __nv_bfloat16* __restrict__ lo, int K) {
    int i = blockIdx.x * 256 + threadIdx.x;
    if (i >= 128 * 512) return;
    int n = i >> 9, k = i & 511;
    float v = (k < K) ? W[n * K + k] : 0.0f;
    __nv_bfloat16 h = __float2bfloat16(v);
    hi[i] = h;
    lo[i] = __float2bfloat16(v - __bfloat162float(h));
}

// ---------------- split-bf16 HMMA GEMM (R12 config: 8 warps, 32x64 warp tile) ----------------
// Ah[row, 0:128] = X[row,:] @ W^T (UNSCALED), fp32 accum via hi/lo split, fp16 output.
// Double-buffered smem, single sync per chunk (store -> LDG(ch+1) -> sync -> MMA).
#define LDB 80
#define TILE_B (128 * LDB)          // 10240
#define CH_BUF (4 * TILE_B)         // 40960: [XHI, XLO, WHI, WLO]
#define GEMM_SMEM (2 * CH_BUF)      // 81920

template <int K>
__global__ __launch_bounds__(256, 1) void k_gemm_mma(const float* __restrict__ X,
                                                     const __nv_bfloat16* __restrict__ Whi,
                                                     const __nv_bfloat16* __restrict__ Wlo,
                                                     __half* __restrict__ Ah) {
    extern __shared__ __align__(16) char smem[];
    const uint32_t sb = s2u(smem);
    const int t = threadIdx.x;
    const int lane = t & 31, wid = t >> 5;
    const int wm = wid >> 1, wn = wid & 1;
    const int m0 = blockIdx.x * 128;
    const int NT = (K + 31) / 32;

    const int crow = t >> 1;
    const int cko  = (t & 1) * 16;
    const int xr   = m0 + crow;
    const bool rok = xr < N_NODES;
    const float* Xrow = X + (size_t)xr * K;
    const uint32_t cbase = (uint32_t)crow * LDB + (uint32_t)cko * 2;

    const int a_row  = lane & 15;
    const int a_koff = ((lane >> 4) & 1) * 16;
    const int b_row  = ((lane >> 4) & 1) * 8 + (lane & 7);
    const int b_koff = ((lane >> 3) & 1) * 16;

    float c[2][8][4];
    #pragma unroll
    for (int i = 0; i < 2; i++)
        #pragma unroll
        for (int j = 0; j < 8; j++)
            #pragma unroll
            for (int q = 0; q < 4; q++) c[i][j][q] = 0.0f;

    float v[16];
    uint4 pwh[2], pwl[2];

#define LOADX(CH) do {                                                          \
        const int ks_ = (CH) * 32 + cko;                                        \
        if (rok && ks_ + 16 <= K) {                                             \
            _Pragma("unroll")                                                   \
            for (int q = 0; q < 4; q++) {                                       \
                float4 f = *(const float4*)(Xrow + ks_ + q * 4);                \
                v[q * 4 + 0] = f.x; v[q * 4 + 1] = f.y;                         \
                v[q * 4 + 2] = f.z; v[q * 4 + 3] = f.w;                         \
            }                                                                   \
        } else {                                                                \
            _Pragma("unroll")                                                   \
            for (int q = 0; q < 16; q++)                                        \
                v[q] = (rok && (ks_ + q) < K) ? Xrow[ks_ + q] : 0.0f;           \
        }                                                                       \
        const __nv_bfloat16* wh_ = Whi + (size_t)crow * 512 + (CH) * 32 + cko;  \
        const __nv_bfloat16* wl_ = Wlo + (size_t)crow * 512 + (CH) * 32 + cko;  \
        pwh[0] = *(const uint4*)(wh_);  pwh[1] = *(const uint4*)(wh_ + 8);      \
        pwl[0] = *(const uint4*)(wl_);  pwl[1] = *(const uint4*)(wl_ + 8);      \
    } while (0)

    LOADX(0);

    for (int ch = 0; ch < NT; ch++) {
        const uint32_t bo = (uint32_t)(ch & 1) * CH_BUF;

        // ---- convert chunk ch (regs) -> split bf16 tiles in buf[ch&1] ----
        {
            uint32_t hh[8], ll[8];
            #pragma unroll
            for (int p = 0; p < 8; p++) {
                __nv_bfloat16 ha = __float2bfloat16(v[2 * p]);
                __nv_bfloat16 hb = __float2bfloat16(v[2 * p + 1]);
                __nv_bfloat16 la = __float2bfloat16(v[2 * p]     - __bfloat162float(ha));
                __nv_bfloat16 lb = __float2bfloat16(v[2 * p + 1] - __bfloat162float(hb));
                hh[p] = (uint32_t)__bfloat16_as_ushort(ha) | ((uint32_t)__bfloat16_as_ushort(hb) << 16);
                ll[p] = (uint32_t)__bfloat16_as_ushort(la) | ((uint32_t)__bfloat16_as_ushort(lb) << 16);
            }
            char* base = smem + bo + cbase;
            *(uint4*)(base)                       = make_uint4(hh[0], hh[1], hh[2], hh[3]);
            *(uint4*)(base + 16)                  = make_uint4(hh[4], hh[5], hh[6], hh[7]);
            *(uint4*)(base + TILE_B)              = make_uint4(ll[0], ll[1], ll[2], ll[3]);
            *(uint4*)(base + TILE_B + 16)         = make_uint4(ll[4], ll[5], ll[6], ll[7]);
            *(uint4*)(base + 2 * TILE_B)          = pwh[0];
            *(uint4*)(base + 2 * TILE_B + 16)     = pwh[1];
            *(uint4*)(base + 3 * TILE_B)          = pwl[0];
            *(uint4*)(base + 3 * TILE_B + 16)     = pwl[1];
        }

        // ---- issue next chunk's global loads (consumed next iteration) ----
        if (ch + 1 < NT) LOADX(ch + 1);

        __syncthreads();

        // ---- MMA on buf[ch&1] ----
        #pragma unroll
        for (int kb = 0; kb < 2; kb++) {
            uint32_t ah[2][4], al[2][4], bh[8][2], bl[8][2];
            #pragma unroll
            for (int mt = 0; mt < 2; mt++) {
                uint32_t ro = (uint32_t)(wm * 32 + mt * 16 + a_row) * LDB + kb * 32 + a_koff;
                ldsm4(ah[mt][0], ah[mt][1], ah[mt][2], ah[mt][3], sb + bo + ro);
                ldsm4(al[mt][0], al[mt][1], al[mt][2], al[mt][3], sb + bo + TILE_B + ro);
            }
            #pragma unroll
            for (int p = 0; p < 4; p++) {
                uint32_t ro = (uint32_t)(wn * 64 + p * 16 + b_row) * LDB + kb * 32 + b_koff;
                uint32_t r0, r1, r2, r3;
                ldsm4(r0, r1, r2, r3, sb + bo + 2 * TILE_B + ro);
                bh[2 * p][0] = r0; bh[2 * p][1] = r1;
                bh[2 * p + 1][0] = r2; bh[2 * p + 1][1] = r3;
                ldsm4(r0, r1, r2, r3, sb + bo + 3 * TILE_B + ro);
                bl[2 * p][0] = r0; bl[2 * p][1] = r1;
                bl[2 * p + 1][0] = r2; bl[2 * p + 1][1] = r3;
            }
            #pragma unroll
            for (int mt = 0; mt < 2; mt++)
                #pragma unroll
                for (int nt = 0; nt < 8; nt++) {
                    mma16816(c[mt][nt], ah[mt], bh[nt]);
                    mma16816(c[mt][nt], ah[mt], bl[nt]);
                    mma16816(c[mt][nt], al[mt], bh[nt]);
                }
        }
    }
#undef LOADX

    // ---- epilogue: store fp16 (no scaling; inv applied in aggregation) ----
    #pragma unroll
    for (int mt = 0; mt < 2; mt++)
        #pragma unroll
        for (int g2 = 0; g2 < 2; g2++) {
            int row = m0 + wm * 32 + mt * 16 + (lane >> 2) + g2 * 8;
            if (row < N_NODES) {
                __half* pr = Ah + (size_t)row * F1 + wn * 64 + (lane & 3) * 2;
                #pragma unroll
                for (int nt = 0; nt < 8; nt++) {
                    __half2 o = __floats2half2_rn(c[mt][nt][g2 * 2 + 0],
                                                  c[mt][nt][g2 * 2 + 1]);
                    *(__half2*)(pr + nt * 8) = o;
                }
            }
        }
}

// ---------------- half2 gather helper ----------------
__device__ __forceinline__ float4 ld_row4(const uint2* A2, int row, int lane) {
    uint2 u = A2[(size_t)row * 32 + lane];
    float2 f0 = __half22float2(*(__half2*)&u.x);
    float2 f1 = __half22float2(*(__half2*)&u.y);
    return make_float4(f0.x, f0.y, f1.x, f1.y);
}

// ---------------- layer-1 aggregation: acc = sum inv[src]*h[src] (+self), relu(inv*acc) ----------------
__global__ __launch_bounds__(256) void k_agg1() {
    long long t = (long long)blockIdx.x * blockDim.x + threadIdx.x;
    int w    = (int)(t >> 5);
    int lane = (int)(t & 31);
    if (w >= N_NODES) return;
    const uint2* A2 = (const uint2*)g_Ah;
    float s = g_inv[w];

    float4 v = ld_row4(A2, w, lane);
    float4 acc = make_float4(v.x * s, v.y * s, v.z * s, v.w * s);   // self loop

    int p  = g_start[w];
    int s1 = g_start[w + 1];
    for (; p + 4 <= s1; p += 4) {
        int i0 = g_srcl[p], i1 = g_srcl[p + 1], i2 = g_srcl[p + 2], i3 = g_srcl[p + 3];
        float w0 = g_inv[i0], w1 = g_inv[i1], w2 = g_inv[i2], w3 = g_inv[i3];
        float4 v0 = ld_row4(A2, i0, lane);
        float4 v1 = ld_row4(A2, i1, lane);
        float4 v2 = ld_row4(A2, i2, lane);
        float4 v3 = ld_row4(A2, i3, lane);
        acc.x += (v0.x * w0 + v1.x * w1) + (v2.x * w2 + v3.x * w3);
        acc.y += (v0.y * w0 + v1.y * w1) + (v2.y * w2 + v3.y * w3);
        acc.z += (v0.z * w0 + v1.z * w1) + (v2.z * w2 + v3.z * w3);
        acc.w += (v0.w * w0 + v1.w * w1) + (v2.w * w2 + v3.w * w3);
    }
    for (; p < s1; p++) {
        int i = g_srcl[p];
        float wi = g_inv[i];
        float4 u = ld_row4(A2, i, lane);
        acc.x += u.x * wi; acc.y += u.y * wi; acc.z += u.z * wi; acc.w += u.w * wi;
    }
    acc.x = fmaxf(acc.x * s, 0.f);
    acc.y = fmaxf(acc.y * s, 0.f);
    acc.z = fmaxf(acc.z * s, 0.f);
    acc.w = fmaxf(acc.w * s, 0.f);
    ((float4*)g_C)[(size_t)w * 32 + lane] = acc;
}

// ---------------- layer-2 aggregation + fused linear head ----------------
__global__ __launch_bounds__(256) void k_agg2(const float* __restrict__ Wlin,
                                              float* __restrict__ out) {
    __shared__ __align__(16) float Wl[NCLS * F1];
    int t = threadIdx.x;
    #pragma unroll
    for (int i = 0; i < 8; i++) Wl[t + i * 256] = Wlin[t + i * 256];
    __syncthreads();

    int w    = blockIdx.x * 8 + (t >> 5);
    int lane = t & 31;
    if (w >= N_NODES) return;
    const uint2* A2 = (const uint2*)g_Ah;
    float s = g_inv[w];

    float4 v = ld_row4(A2, w, lane);
    float4 acc = make_float4(v.x * s, v.y * s, v.z * s, v.w * s);

    int p  = g_start[w];
    int s1 = g_start[w + 1];
    for (; p + 4 <= s1; p += 4) {
        int i0 = g_srcl[p], i1 = g_srcl[p + 1], i2 = g_srcl[p + 2], i3 = g_srcl[p + 3];
        float w0 = g_inv[i0], w1 = g_inv[i1], w2 = g_inv[i2], w3 = g_inv[i3];
        float4 v0 = ld_row4(A2, i0, lane);
        float4 v1 = ld_row4(A2, i1, lane);
        float4 v2 = ld_row4(A2, i2, lane);
        float4 v3 = ld_row4(A2, i3, lane);
        acc.x += (v0.x * w0 + v1.x * w1) + (v2.x * w2 + v3.x * w3);
        acc.y += (v0.y * w0 + v1.y * w1) + (v2.y * w2 + v3.y * w3);
        acc.z += (v0.z * w0 + v1.z * w1) + (v2.z * w2 + v3.z * w3);
        acc.w += (v0.w * w0 + v1.w * w1) + (v2.w * w2 + v3.w * w3);
    }
    for (; p < s1; p++) {
        int i = g_srcl[p];
        float wi = g_inv[i];
        float4 u = ld_row4(A2, i, lane);
        acc.x += u.x * wi; acc.y += u.y * wi; acc.z += u.z * wi; acc.w += u.w * wi;
    }
    acc.x *= s; acc.y *= s; acc.z *= s; acc.w *= s;

    #pragma unroll
    for (int cc = 0; cc < NCLS; cc++) {
        float4 wv = *(const float4*)&Wl[cc * F1 + lane * 4];
        float pd = acc.x * wv.x + acc.y * wv.y + acc.z * wv.z + acc.w * wv.w;
        pd += __shfl_xor_sync(0xffffffffu, pd, 16);
        pd += __shfl_xor_sync(0xffffffffu, pd, 8);
        pd += __shfl_xor_sync(0xffffffffu, pd, 4);
        pd += __shfl_xor_sync(0xffffffffu, pd, 2);
        pd += __shfl_xor_sync(0xffffffffu, pd, 1);
        if (lane == 0) out[(size_t)w * NCLS + cc] = pd;
    }
}

// ---------------- launch: fork GEMM1 branch parallel to CSR build ----------------
extern "C" void kernel_launch(void* const* d_in, const int* in_sizes, int n_in,
                              void* d_out, int out_size) {
    const float* x    = (const float*)d_in[0];
    const void*  ei   = d_in[1];
    const float* W1   = (const float*)d_in[2];
    const float* W2   = (const float*)d_in[3];
    const float* Wlin = (const float*)d_in[4];
    float* out = (float*)d_out;

    long long E = (long long)in_sizes[1] / 2;

    __half* Ah;
    float* C;
    __nv_bfloat16 *w1h, *w1l, *w2h, *w2l;
    cudaGetSymbolAddress((void**)&Ah, g_Ah);
    cudaGetSymbolAddress((void**)&C, g_C);
    cudaGetSymbolAddress((void**)&w1h, g_W1hi);
    cudaGetSymbolAddress((void**)&w1l, g_W1lo);
    cudaGetSymbolAddress((void**)&w2h, g_W2hi);
    cudaGetSymbolAddress((void**)&w2l, g_W2lo);

    cudaFuncSetAttribute(k_gemm_mma<500>, cudaFuncAttributeMaxDynamicSharedMemorySize, GEMM_SMEM);
    cudaFuncSetAttribute(k_gemm_mma<128>, cudaFuncAttributeMaxDynamicSharedMemorySize, GEMM_SMEM);

    const int T = 256;
    int nodeBlocks = (N_NODES + T - 1) / T;
    int gemmBlocks = (N_NODES + 127) / 128;   // 391
    int edgeBlocks = (int)((E + T - 1) / T);
    int aggBlocks  = (int)(((long long)N_NODES * 32 + T - 1) / T);
    int wsBlocks   = (128 * 512 + T - 1) / T;

    // Fork-join inside graph capture: side stream sB carries the W-split + GEMM1
    // branch (touches only g_W* and g_Ah) while the main stream builds the CSR.
    // Host-side stream/event create/destroy happen at capture time only; the
    // replayed graph contains just the kernels + dependency edges.
    cudaStream_t sB;
    cudaStreamCreateWithFlags(&sB, cudaStreamNonBlocking);
    cudaEvent_t e0, e1;
    cudaEventCreateWithFlags(&e0, cudaEventDisableTiming);
    cudaEventCreateWithFlags(&e1, cudaEventDisableTiming);

    // branch point at entry (GEMM1 branch has no dependency on main-stream work)
    cudaEventRecord(e0, 0);
    cudaStreamWaitEvent(sB, e0, 0);

    k_init<<<nodeBlocks, T>>>((const int*)ei);                              // 0 (s0)
    k_wsplit<<<wsBlocks, T, 0, sB>>>(W1, w1h, w1l, 500);                    // 1 (sB)
    k_gemm_mma<500><<<gemmBlocks, T, GEMM_SMEM, sB>>>(x, w1h, w1l, Ah);     // 2 (sB)
    k_hist<<<edgeBlocks, T>>>(ei, E);                                       // 3 (s0) <- profiled
    k_wsplit<<<wsBlocks, T, 0, sB>>>(W2, w2h, w2l, 128);                    // 4 (sB)
    cudaEventRecord(e1, sB);
    k_scan1<<<NB_SCAN, T>>>();                                              // 5 (s0)
    k_scan2<<<1, T>>>();                                                    // 6 (s0)
    k_scan3<<<NB_SCAN, T>>>();                                              // 7 (s0)
    k_fill<<<edgeBlocks, T>>>(ei, E);                                       // 8 (s0)
    cudaStreamWaitEvent(0, e1, 0);                                          // join
    k_agg1<<<aggBlocks, T>>>();                                             // 9 (s0)
    k_gemm_mma<128><<<gemmBlocks, T, GEMM_SMEM>>>(C, w2h, w2l, Ah);         // 10 (s0)
    k_agg2<<<(N_NODES + 7) / 8, T>>>(Wlin, out);                            // 11 (s0)

    cudaStreamDestroy(sB);
    cudaEventDestroy(e0);
    cudaEventDestroy(e1);
}

// round 16
// speedup vs baseline: 1.2141x; 1.0539x over previous
#include <cuda_runtime.h>
#include <cuda_bf16.h>
#include <cuda_fp16.h>
#include <cstdint>

#define N_NODES 50000
#define F1 128
#define NCLS 16
#define EMAX 1600000
#define NB_SCAN ((N_NODES + 255) / 256)   // 196

// ---------------- scratch (static device globals; no allocation) ----------------
__device__ int    g_cnt[N_NODES];
__device__ int    g_start[N_NODES + 1];
__device__ int    g_cursor[N_NODES];
__device__ int    g_srcl[EMAX];
__device__ float  g_inv[N_NODES];
__device__ __half g_Ah[N_NODES * F1];     // layer1 gemm output h (UNSCALED), fp16
__device__ float  g_C[N_NODES * F1];      // relu(layer1 aggregate), fp32
__device__ float  g_z[N_NODES * NCLS];    // z = h2 @ Wlin^T, fp32
__device__ int    g_bsum[256];
__device__ int    g_boff[256];
__device__ int    g_is64;
// pre-split weights, padded to K=512, layout [n][512] bf16
__device__ __nv_bfloat16 g_W1hi[128 * 512];
__device__ __nv_bfloat16 g_W1lo[128 * 512];
__device__ __nv_bfloat16 g_W2hi[128 * 512];
__device__ __nv_bfloat16 g_W2lo[128 * 512];

// ---------------- mma/ldmatrix wrappers (base ISA, sm_80+) ----------------
__device__ __forceinline__ uint32_t s2u(const void* p) {
    uint32_t a;
    asm("{ .reg .u64 t; cvta.to.shared.u64 t, %1; cvt.u32.u64 %0, t; }" : "=r"(a) : "l"(p));
    return a;
}
__device__ __forceinline__ void ldsm4(uint32_t& r0, uint32_t& r1, uint32_t& r2, uint32_t& r3,
                                      uint32_t addr) {
    asm volatile("ldmatrix.sync.aligned.m8n8.x4.shared.b16 {%0,%1,%2,%3}, [%4];"
                 : "=r"(r0), "=r"(r1), "=r"(r2), "=r"(r3) : "r"(addr));
}
__device__ __forceinline__ void mma16816(float* c, const uint32_t* a, const uint32_t* b) {
    asm volatile(
        "mma.sync.aligned.m16n8k16.row.col.f32.bf16.bf16.f32 "
        "{%0,%1,%2,%3}, {%4,%5,%6,%7}, {%8,%9}, {%0,%1,%2,%3};"
        : "+f"(c[0]), "+f"(c[1]), "+f"(c[2]), "+f"(c[3])
        : "r"(a[0]), "r"(a[1]), "r"(a[2]), "r"(a[3]), "r"(b[0]), "r"(b[1]));
}

// ---------------- fused init: zero counts + dtype detect ----------------
__global__ void k_init(const int* ei) {
    int i = blockIdx.x * blockDim.x + threadIdx.x;
    if (i < N_NODES) g_cnt[i] = 0;
    if (i == 0) {
        int ok64 = 1;
        #pragma unroll 1
        for (int q = 0; q < 64; q++) ok64 &= (ei[2 * q + 1] == 0);
        g_is64 = ok64;
    }
}

// ---------------- CSR build ----------------
__global__ __launch_bounds__(256) void k_hist(const void* idx, long long E) {
    long long e = (long long)blockIdx.x * blockDim.x + threadIdx.x;
    if (e >= E) return;
    int d;
    if (g_is64) d = (int)((const long long*)idx)[E + e];
    else        d = ((const int*)idx)[E + e];
    atomicAdd(&g_cnt[d], 1);
}

__global__ __launch_bounds__(256) void k_scan1() {
    int i = blockIdx.x * 256 + threadIdx.x;
    int lane = threadIdx.x & 31, wid = threadIdx.x >> 5;
    int c = (i < N_NODES) ? g_cnt[i] : 0;
    int s = c;
    #pragma unroll
    for (int off = 16; off; off >>= 1) s += __shfl_xor_sync(0xffffffffu, s, off);
    __shared__ int ws[8];
    if (lane == 0) ws[wid] = s;
    __syncthreads();
    if (threadIdx.x == 0) {
        int tot = 0;
        #pragma unroll
        for (int w = 0; w < 8; w++) tot += ws[w];
        g_bsum[blockIdx.x] = tot;
    }
}

__global__ __launch_bounds__(256) void k_scan2() {
    __shared__ int s[256];
    int t = threadIdx.x;
    int v = (t < NB_SCAN) ? g_bsum[t] : 0;
    s[t] = v;
    __syncthreads();
    for (int off = 1; off < 256; off <<= 1) {
        int u = (t >= off) ? s[t - off] : 0;
        __syncthreads();
        s[t] += u;
        __syncthreads();
    }
    g_boff[t] = s[t] - v;
    if (t == 255) g_start[N_NODES] = s[255];
}

__global__ __launch_bounds__(256) void k_scan3() {
    int i = blockIdx.x * 256 + threadIdx.x;
    int t = threadIdx.x, lane = t & 31, wid = t >> 5;
    int c = (i < N_NODES) ? g_cnt[i] : 0;
    int incl = c;
    #pragma unroll
    for (int off = 1; off < 32; off <<= 1) {
        int u = __shfl_up_sync(0xffffffffu, incl, off);
        if (lane >= off) incl += u;
    }
    __shared__ int ws[8];
    if (lane == 31) ws[wid] = incl;
    __syncthreads();
    if (t == 0) {
        int run = 0;
        #pragma unroll
        for (int w = 0; w < 8; w++) { int x = ws[w]; ws[w] = run; run += x; }
    }
    __syncthreads();
    if (i < N_NODES) {
        int excl = incl - c + ws[wid] + g_boff[blockIdx.x];
        g_start[i]  = excl;
        g_cursor[i] = excl;
        g_inv[i]    = rsqrtf((float)c + 1.0f);
    }
}

__global__ __launch_bounds__(256) void k_fill(const void* idx, long long E) {
    long long e = (long long)blockIdx.x * blockDim.x + threadIdx.x;
    if (e >= E) return;
    int s, d;
    if (g_is64) {
        s = (int)((const long long*)idx)[e];
        d = (int)((const long long*)idx)[E + e];
    } else {
        s = ((const int*)idx)[e];
        d = ((const int*)idx)[E + e];
    }
    int pos = atomicAdd(&g_cursor[d], 1);
    g_srcl[pos] = s;
}

// ---------------- weight pre-split: W[n][k] fp32 -> hi/lo bf16 padded [n][512] ----------------
__global__ __launch_bounds__(256) void k_wsplit(const float* __restrict__ W,
                                                __nv_bfloat16* __restrict__ hi,
                                                __nv_bfloat16* __restrict__ lo, int K) {
    int i = blockIdx.x * 256 + threadIdx.x;
    if (i >= 128 * 512) return;
    int n = i >> 9, k = i & 511;
    float v = (k < K) ? W[n * K + k] : 0.0f;
    __nv_bfloat16 h = __float2bfloat16(v);
    hi[i] = h;
    lo[i] = __float2bfloat16(v - __bfloat162float(h));
}

// ---------------- shared GEMM machinery (R12-verified config) ----------------
#define LDB 80
#define TILE_B (128 * LDB)          // 10240
#define CH_BUF (4 * TILE_B)         // 40960: [XHI, XLO, WHI, WLO]
#define GEMM_SMEM (2 * CH_BUF)      // 81920
#define ROWB 272                    // h2 smem staging row stride (bytes)
#define GEMM2_SMEM (2 * CH_BUF + NCLS * F1 * 4)   // + Wlin 8KB = 90112

// convert + store one chunk of X (regs v[16]) and W (regs) into buffer bo
#define CVT_STORE(bo)                                                            \
    do {                                                                         \
        uint32_t hh[8], ll[8];                                                   \
        _Pragma("unroll")                                                        \
        for (int p = 0; p < 8; p++) {                                            \
            __nv_bfloat16 ha = __float2bfloat16(v[2 * p]);                       \
            __nv_bfloat16 hb = __float2bfloat16(v[2 * p + 1]);                   \
            __nv_bfloat16 la = __float2bfloat16(v[2 * p]     - __bfloat162float(ha)); \
            __nv_bfloat16 lb = __float2bfloat16(v[2 * p + 1] - __bfloat162float(hb)); \
            hh[p] = (uint32_t)__bfloat16_as_ushort(ha) | ((uint32_t)__bfloat16_as_ushort(hb) << 16); \
            ll[p] = (uint32_t)__bfloat16_as_ushort(la) | ((uint32_t)__bfloat16_as_ushort(lb) << 16); \
        }                                                                        \
        char* base = smem + (bo) + cbase;                                        \
        *(uint4*)(base)                   = make_uint4(hh[0], hh[1], hh[2], hh[3]); \
        *(uint4*)(base + 16)              = make_uint4(hh[4], hh[5], hh[6], hh[7]); \
        *(uint4*)(base + TILE_B)          = make_uint4(ll[0], ll[1], ll[2], ll[3]); \
        *(uint4*)(base + TILE_B + 16)     = make_uint4(ll[4], ll[5], ll[6], ll[7]); \
        *(uint4*)(base + 2 * TILE_B)      = pwh[0];                              \
        *(uint4*)(base + 2 * TILE_B + 16) = pwh[1];                              \
        *(uint4*)(base + 3 * TILE_B)      = pwl[0];                              \
        *(uint4*)(base + 3 * TILE_B + 16) = pwl[1];                              \
    } while (0)

#define LOADX(CH, K)                                                            \
    do {                                                                        \
        const int ks_ = (CH) * 32 + cko;                                        \
        if (rok && ks_ + 16 <= (K)) {                                           \
            _Pragma("unroll")                                                   \
            for (int q = 0; q < 4; q++) {                                       \
                float4 f = *(const float4*)(Xrow + ks_ + q * 4);                \
                v[q * 4 + 0] = f.x; v[q * 4 + 1] = f.y;                         \
                v[q * 4 + 2] = f.z; v[q * 4 + 3] = f.w;                         \
            }                                                                   \
        } else {                                                                \
            _Pragma("unroll")                                                   \
            for (int q = 0; q < 16; q++)                                        \
                v[q] = (rok && (ks_ + q) < (K)) ? Xrow[ks_ + q] : 0.0f;         \
        }                                                                       \
        const __nv_bfloat16* wh_ = Whi + (size_t)crow * 512 + (CH) * 32 + cko;  \
        const __nv_bfloat16* wl_ = Wlo + (size_t)crow * 512 + (CH) * 32 + cko;  \
        pwh[0] = *(const uint4*)(wh_);  pwh[1] = *(const uint4*)(wh_ + 8);      \
        pwl[0] = *(const uint4*)(wl_);  pwl[1] = *(const uint4*)(wl_ + 8);      \
    } while (0)

#define MMA_CHUNK(bo)                                                           \
    do {                                                                        \
        _Pragma("unroll")                                                       \
        for (int kb = 0; kb < 2; kb++) {                                        \
            uint32_t ah[2][4], al[2][4], bh[8][2], bl[8][2];                    \
            _Pragma("unroll")                                                   \
            for (int mt = 0; mt < 2; mt++) {                                    \
                uint32_t ro = (uint32_t)(wm * 32 + mt * 16 + a_row) * LDB + kb * 32 + a_koff; \
                ldsm4(ah[mt][0], ah[mt][1], ah[mt][2], ah[mt][3], sb + (bo) + ro);            \
                ldsm4(al[mt][0], al[mt][1], al[mt][2], al[mt][3], sb + (bo) + TILE_B + ro);   \
            }                                                                   \
            _Pragma("unroll")                                                   \
            for (int p = 0; p < 4; p++) {                                       \
                uint32_t ro = (uint32_t)(wn * 64 + p * 16 + b_row) * LDB + kb * 32 + b_koff;  \
                uint32_t r0, r1, r2, r3;                                        \
                ldsm4(r0, r1, r2, r3, sb + (bo) + 2 * TILE_B + ro);             \
                bh[2 * p][0] = r0; bh[2 * p][1] = r1;                           \
                bh[2 * p + 1][0] = r2; bh[2 * p + 1][1] = r3;                   \
                ldsm4(r0, r1, r2, r3, sb + (bo) + 3 * TILE_B + ro);             \
                bl[2 * p][0] = r0; bl[2 * p][1] = r1;                           \
                bl[2 * p + 1][0] = r2; bl[2 * p + 1][1] = r3;                   \
            }                                                                   \
            _Pragma("unroll")                                                   \
            for (int mt = 0; mt < 2; mt++)                                      \
                _Pragma("unroll")                                               \
                for (int nt = 0; nt < 8; nt++) {                                \
                    mma16816(c[mt][nt], ah[mt], bh[nt]);                        \
                    mma16816(c[mt][nt], ah[mt], bl[nt]);                        \
                    mma16816(c[mt][nt], al[mt], bh[nt]);                        \
                }                                                               \
        }                                                                       \
    } while (0)

#define GEMM_PREAMBLE(K)                                                        \
    extern __shared__ __align__(16) char smem[];                                \
    const uint32_t sb = s2u(smem);                                              \
    const int t = threadIdx.x;                                                  \
    const int lane = t & 31, wid = t >> 5;                                      \
    const int wm = wid >> 1, wn = wid & 1;                                      \
    const int m0 = blockIdx.x * 128;                                            \
    const int NT = ((K) + 31) / 32;                                             \
    const int crow = t >> 1;                                                    \
    const int cko  = (t & 1) * 16;                                              \
    const int xr   = m0 + crow;                                                 \
    const bool rok = xr < N_NODES;                                              \
    const float* Xrow = X + (size_t)xr * (K);                                   \
    const uint32_t cbase = (uint32_t)crow * LDB + (uint32_t)cko * 2;            \
    const int a_row  = lane & 15;                                               \
    const int a_koff = ((lane >> 4) & 1) * 16;                                  \
    const int b_row  = ((lane >> 4) & 1) * 8 + (lane & 7);                      \
    const int b_koff = ((lane >> 3) & 1) * 16;                                  \
    float c[2][8][4];                                                           \
    _Pragma("unroll")                                                           \
    for (int i = 0; i < 2; i++)                                                 \
        _Pragma("unroll")                                                       \
        for (int j = 0; j < 8; j++)                                             \
            _Pragma("unroll")                                                   \
            for (int q = 0; q < 4; q++) c[i][j][q] = 0.0f;                      \
    float v[16];                                                                \
    uint4 pwh[2], pwl[2];

// ---------------- GEMM1: Ah = X @ W1^T (fp16 out, unscaled) ----------------
template <int K>
__global__ __launch_bounds__(256, 1) void k_gemm_mma(const float* __restrict__ X,
                                                     const __nv_bfloat16* __restrict__ Whi,
                                                     const __nv_bfloat16* __restrict__ Wlo,
                                                     __half* __restrict__ Ah) {
    GEMM_PREAMBLE(K)

    LOADX(0, K);
    for (int ch = 0; ch < NT; ch++) {
        const uint32_t bo = (uint32_t)(ch & 1) * CH_BUF;
        CVT_STORE(bo);
        if (ch + 1 < NT) LOADX(ch + 1, K);
        __syncthreads();
        MMA_CHUNK(bo);
    }

    #pragma unroll
    for (int mt = 0; mt < 2; mt++)
        #pragma unroll
        for (int g2 = 0; g2 < 2; g2++) {
            int row = m0 + wm * 32 + mt * 16 + (lane >> 2) + g2 * 8;
            if (row < N_NODES) {
                __half* pr = Ah + (size_t)row * F1 + wn * 64 + (lane & 3) * 2;
                #pragma unroll
                for (int nt = 0; nt < 8; nt++) {
                    __half2 o = __floats2half2_rn(c[mt][nt][g2 * 2 + 0],
                                                  c[mt][nt][g2 * 2 + 1]);
                    *(__half2*)(pr + nt * 8) = o;
                }
            }
        }
}

// ---------------- GEMM2 fused z: z = (X @ W2^T) @ Wlin^T, never hits global h2 ----------------
__global__ __launch_bounds__(256, 1) void k_gemm2_z(const float* __restrict__ X,
                                                    const __nv_bfloat16* __restrict__ Whi,
                                                    const __nv_bfloat16* __restrict__ Wlo,
                                                    const float* __restrict__ Wlin,
                                                    float* __restrict__ z) {
    GEMM_PREAMBLE(128)

    // Wlin -> smem above the double buffers
    float* Wls = (float*)(smem + 2 * CH_BUF);
    #pragma unroll
    for (int i = 0; i < 8; i++) Wls[t + i * 256] = Wlin[t + i * 256];

    LOADX(0, 128);
    for (int ch = 0; ch < NT; ch++) {
        const uint32_t bo = (uint32_t)(ch & 1) * CH_BUF;
        CVT_STORE(bo);
        if (ch + 1 < NT) LOADX(ch + 1, 128);
        __syncthreads();
        MMA_CHUNK(bo);
    }

    // ---- stage h2 tile to smem (fp16, row stride ROWB; conflict-free) ----
    __syncthreads();   // all MMA reads retired; buffers reusable
    #pragma unroll
    for (int mt = 0; mt < 2; mt++)
        #pragma unroll
        for (int g2 = 0; g2 < 2; g2++) {
            int row = wm * 32 + mt * 16 + (lane >> 2) + g2 * 8;
            char* pr = smem + row * ROWB + (wn * 64 + (lane & 3) * 2) * 2;
            #pragma unroll
            for (int nt = 0; nt < 8; nt++) {
                __half2 o = __floats2half2_rn(c[mt][nt][g2 * 2 + 0],
                                              c[mt][nt][g2 * 2 + 1]);
                *(__half2*)(pr + nt * 16) = o;
            }
        }
    __syncthreads();

    // ---- z: warp per row (16 rows/warp), dot with Wlin + shfl reduce ----
    #pragma unroll 1
    for (int r8 = 0; r8 < 16; r8++) {
        int row = wid * 16 + r8;
        int grow = m0 + row;
        uint2 u = *(uint2*)(smem + row * ROWB + lane * 8);
        float2 f0 = __half22float2(*(__half2*)&u.x);
        float2 f1 = __half22float2(*(__half2*)&u.y);
        #pragma unroll
        for (int cc = 0; cc < NCLS; cc++) {
            float4 wv = *(const float4*)&Wls[cc * F1 + lane * 4];
            float pd = f0.x * wv.x + f0.y * wv.y + f1.x * wv.z + f1.y * wv.w;
            pd += __shfl_xor_sync(0xffffffffu, pd, 16);
            pd += __shfl_xor_sync(0xffffffffu, pd, 8);
            pd += __shfl_xor_sync(0xffffffffu, pd, 4);
            pd += __shfl_xor_sync(0xffffffffu, pd, 2);
            pd += __shfl_xor_sync(0xffffffffu, pd, 1);
            if (lane == 0 && grow < N_NODES) z[(size_t)grow * NCLS + cc] = pd;
        }
    }
}

// ---------------- half2 gather helper ----------------
__device__ __forceinline__ float4 ld_row4(const uint2* A2, int row, int lane) {
    uint2 u = A2[(size_t)row * 32 + lane];
    float2 f0 = __half22float2(*(__half2*)&u.x);
    float2 f1 = __half22float2(*(__half2*)&u.y);
    return make_float4(f0.x, f0.y, f1.x, f1.y);
}

// ---------------- layer-1 aggregation: C = relu(inv*(sum inv[src]*h[src] + self)) ----------------
__global__ __launch_bounds__(256) void k_agg1() {
    long long t = (long long)blockIdx.x * blockDim.x + threadIdx.x;
    int w    = (int)(t >> 5);
    int lane = (int)(t & 31);
    if (w >= N_NODES) return;
    const uint2* A2 = (const uint2*)g_Ah;
    float s = g_inv[w];

    float4 v = ld_row4(A2, w, lane);
    float4 acc = make_float4(v.x * s, v.y * s, v.z * s, v.w * s);   // self loop

    int p  = g_start[w];
    int s1 = g_start[w + 1];
    for (; p + 4 <= s1; p += 4) {
        int i0 = g_srcl[p], i1 = g_srcl[p + 1], i2 = g_srcl[p + 2], i3 = g_srcl[p + 3];
        float w0 = g_inv[i0], w1 = g_inv[i1], w2 = g_inv[i2], w3 = g_inv[i3];
        float4 v0 = ld_row4(A2, i0, lane);
        float4 v1 = ld_row4(A2, i1, lane);
        float4 v2 = ld_row4(A2, i2, lane);
        float4 v3 = ld_row4(A2, i3, lane);
        acc.x += (v0.x * w0 + v1.x * w1) + (v2.x * w2 + v3.x * w3);
        acc.y += (v0.y * w0 + v1.y * w1) + (v2.y * w2 + v3.y * w3);
        acc.z += (v0.z * w0 + v1.z * w1) + (v2.z * w2 + v3.z * w3);
        acc.w += (v0.w * w0 + v1.w * w1) + (v2.w * w2 + v3.w * w3);
    }
    for (; p < s1; p++) {
        int i = g_srcl[p];
        float wi = g_inv[i];
        float4 u = ld_row4(A2, i, lane);
        acc.x += u.x * wi; acc.y += u.y * wi; acc.z += u.z * wi; acc.w += u.w * wi;
    }
    acc.x = fmaxf(acc.x * s, 0.f);
    acc.y = fmaxf(acc.y * s, 0.f);
    acc.z = fmaxf(acc.z * s, 0.f);
    acc.w = fmaxf(acc.w * s, 0.f);
    ((float4*)g_C)[(size_t)w * 32 + lane] = acc;
}

// ---------------- layer-2 aggregation in z-space (16-wide rows), half-warp per dst ----------------
__global__ __launch_bounds__(256) void k_agg2z(float* __restrict__ out) {
    int t = threadIdx.x;
    int w = blockIdx.x * 16 + (t >> 4);
    int l16 = t & 15;
    if (w >= N_NODES) return;
    const float* Z = g_z;
    float s = g_inv[w];

    float acc = Z[(size_t)w * NCLS + l16] * s;   // self loop
    int p  = g_start[w];
    int s1 = g_start[w + 1];
    for (; p + 4 <= s1; p += 4) {
        int i0 = g_srcl[p], i1 = g_srcl[p + 1], i2 = g_srcl[p + 2], i3 = g_srcl[p + 3];
        float a0 = g_inv[i0] * Z[(size_t)i0 * NCLS + l16];
        float a1 = g_inv[i1] * Z[(size_t)i1 * NCLS + l16];
        float a2 = g_inv[i2] * Z[(size_t)i2 * NCLS + l16];
        float a3 = g_inv[i3] * Z[(size_t)i3 * NCLS + l16];
        acc += (a0 + a1) + (a2 + a3);
    }
    for (; p < s1; p++) {
        int i = g_srcl[p];
        acc += g_inv[i] * Z[(size_t)i * NCLS + l16];
    }
    out[(size_t)w * NCLS + l16] = acc * s;
}

// ---------------- launch: fork GEMM1 branch parallel to CSR build ----------------
extern "C" void kernel_launch(void* const* d_in, const int* in_sizes, int n_in,
                              void* d_out, int out_size) {
    const float* x    = (const float*)d_in[0];
    const void*  ei   = d_in[1];
    const float* W1   = (const float*)d_in[2];
    const float* W2   = (const float*)d_in[3];
    const float* Wlin = (const float*)d_in[4];
    float* out = (float*)d_out;

    long long E = (long long)in_sizes[1] / 2;

    __half* Ah;
    float *C, *Zp;
    __nv_bfloat16 *w1h, *w1l, *w2h, *w2l;
    cudaGetSymbolAddress((void**)&Ah, g_Ah);
    cudaGetSymbolAddress((void**)&C, g_C);
    cudaGetSymbolAddress((void**)&Zp, g_z);
    cudaGetSymbolAddress((void**)&w1h, g_W1hi);
    cudaGetSymbolAddress((void**)&w1l, g_W1lo);
    cudaGetSymbolAddress((void**)&w2h, g_W2hi);
    cudaGetSymbolAddress((void**)&w2l, g_W2lo);

    cudaFuncSetAttribute(k_gemm_mma<500>, cudaFuncAttributeMaxDynamicSharedMemorySize, GEMM_SMEM);
    cudaFuncSetAttribute(k_gemm2_z, cudaFuncAttributeMaxDynamicSharedMemorySize, GEMM2_SMEM);

    const int T = 256;
    int nodeBlocks = (N_NODES + T - 1) / T;
    int gemmBlocks = (N_NODES + 127) / 128;   // 391
    int edgeBlocks = (int)((E + T - 1) / T);
    int aggBlocks  = (int)(((long long)N_NODES * 32 + T - 1) / T);
    int agg2Blocks = (N_NODES + 15) / 16;
    int wsBlocks   = (128 * 512 + T - 1) / T;

    // Fork-join inside graph capture (validated R14 pattern).
    cudaStream_t sB;
    cudaStreamCreateWithFlags(&sB, cudaStreamNonBlocking);
    cudaEvent_t e0, e1;
    cudaEventCreateWithFlags(&e0, cudaEventDisableTiming);
    cudaEventCreateWithFlags(&e1, cudaEventDisableTiming);

    cudaEventRecord(e0, 0);
    cudaStreamWaitEvent(sB, e0, 0);

    k_init<<<nodeBlocks, T>>>((const int*)ei);                              // s0 #1
    k_wsplit<<<wsBlocks, T, 0, sB>>>(W1, w1h, w1l, 500);                    // sB #2
    k_hist<<<edgeBlocks, T>>>(ei, E);                                       // s0 #3
    k_gemm_mma<500><<<gemmBlocks, T, GEMM_SMEM, sB>>>(x, w1h, w1l, Ah);     // sB #4 <- profiled
    cudaEventRecord(e1, sB);
    k_scan1<<<NB_SCAN, T>>>();                                              // s0
    k_scan2<<<1, T>>>();                                                    // s0
    k_scan3<<<NB_SCAN, T>>>();                                              // s0
    k_fill<<<edgeBlocks, T>>>(ei, E);                                       // s0
    k_wsplit<<<wsBlocks, T>>>(W2, w2h, w2l, 128);                           // s0 (hidden)
    cudaStreamWaitEvent(0, e1, 0);                                          // join
    k_agg1<<<aggBlocks, T>>>();                                             // s0
    k_gemm2_z<<<gemmBlocks, T, GEMM2_SMEM>>>(C, w2h, w2l, Wlin, Zp);        // s0
    k_agg2z<<<agg2Blocks, T>>>(out);                                        // s0

    cudaStreamDestroy(sB);
    cudaEventDestroy(e0);
    cudaEventDestroy(e1);
}